// round 7
// baseline (speedup 1.0000x reference)
#include <cuda_runtime.h>
#include <cuda_bf16.h>
#include <cstdint>
#include <cstddef>

// ---------------- Problem constants ----------------
#define BATCH    16384
#define EMB      64
#define NSP      26
#define NFEAT    28            // user + item + 26 sparse
#define KDIM     1792
#define NDIM     128
#define SPVOC    100000
#define TILE_M   64
#define NTH      128           // 4 warps: (warp>>1)=row group (32 rows), (warp&1)=n half
#define NBSTG    3             // B cp.async ring stages
#define A_STR    72            // bf16 row stride (64 + 8 pad) -> conflict-free
#define B_STR    72

#define SMEM_A_BYTES   (2 * TILE_M * A_STR * 2)            // 18432
#define SMEM_B_BYTES   (NBSTG * NDIM * B_STR * 2)          // 55296
#define SMEM_IDX_BYTES (TILE_M * NFEAT * 4)                // 7168
#define SMEM_PART_BYTES (TILE_M * 2 * 4)                   // 512
#define SMEM_TOTAL (SMEM_A_BYTES + SMEM_B_BYTES + SMEM_IDX_BYTES + SMEM_PART_BYTES)

// Pre-transposed bf16 copy of W1: g_W1T[n][k]  (n-major, k contiguous)
__device__ __nv_bfloat16 g_W1T[NDIM * KDIM];

__global__ void prep_w1_kernel(const float* __restrict__ W1) {
    int i = blockIdx.x * blockDim.x + threadIdx.x;
    if (i < NDIM * KDIM) {
        int n = i / KDIM;
        int k = i - n * KDIM;
        g_W1T[i] = __float2bfloat16(W1[(size_t)k * NDIM + n]);
    }
}

// ---------------- PTX helpers ----------------
__device__ __forceinline__ void cpa16(void* smem, const void* gmem) {
    uint32_t s = (uint32_t)__cvta_generic_to_shared(smem);
    asm volatile("cp.async.cg.shared.global [%0], [%1], 16;\n" :: "r"(s), "l"(gmem));
}
__device__ __forceinline__ void cpa_commit() {
    asm volatile("cp.async.commit_group;\n" ::: "memory");
}
__device__ __forceinline__ void cpa_wait1() {
    asm volatile("cp.async.wait_group 1;\n" ::: "memory");
}
__device__ __forceinline__ uint32_t pack_bf16x2(float x, float y) {
    __nv_bfloat162 h = __floats2bfloat162_rn(x, y);
    return *(uint32_t*)&h;
}

__global__ __launch_bounds__(NTH, 2) void dlrm_fused_kernel(
    const int*   __restrict__ user_ids,
    const int*   __restrict__ item_ids,
    const int*   __restrict__ sparse,
    const float* __restrict__ user_emb,
    const float* __restrict__ item_emb,
    const float* __restrict__ sparse_tables,
    const float* __restrict__ b1,
    const float* __restrict__ W2,
    const float* __restrict__ b2,
    float*       __restrict__ out)
{
    extern __shared__ char smem_raw[];
    __nv_bfloat16* sA   = (__nv_bfloat16*)smem_raw;                  // [2][64][A_STR]
    __nv_bfloat16* sB   = (__nv_bfloat16*)(smem_raw + SMEM_A_BYTES); // [3][128][B_STR]
    int*           sIdx = (int*)(smem_raw + SMEM_A_BYTES + SMEM_B_BYTES);
    float*         sPart= (float*)(smem_raw + SMEM_A_BYTES + SMEM_B_BYTES + SMEM_IDX_BYTES);

    const int tid  = threadIdx.x;
    const int warp = tid >> 5;
    const int lane = tid & 31;
    const int row0 = blockIdx.x * TILE_M;

    const int g    = lane >> 2;        // 0..7
    const int tg   = lane & 3;         // 0..3
    const int wmb  = (warp >> 1) * 32; // row-group base (0 or 32)
    const int nh   = warp & 1;         // n half (64 cols)

    // ---- Preload all 64x28 indices into SMEM (one round trip)
    #pragma unroll
    for (int j = 0; j < 14; ++j) {
        int linear = tid + j * NTH;          // < 1792
        int r = linear / NFEAT;
        int f = linear - r * NFEAT;
        int v;
        if (f == 0)      v = __ldg(user_ids + row0 + r);
        else if (f == 1) v = __ldg(item_ids + row0 + r);
        else             v = __ldg(sparse + (size_t)(row0 + r) * NSP + (f - 2));
        sIdx[r * NFEAT + f] = v;
    }
    __syncthreads();

    // accumulators: 2 m-tiles x 8 n-tiles x 4
    float c[2][8][4];
    #pragma unroll
    for (int mt = 0; mt < 2; ++mt)
        #pragma unroll
        for (int nt = 0; nt < 8; ++nt) {
            c[mt][nt][0] = 0.f; c[mt][nt][1] = 0.f;
            c[mt][nt][2] = 0.f; c[mt][nt][3] = 0.f;
        }

    // ---- A gather: 8 float4 per thread per feature, 2-ahead reg double buffer
    float4 abuf[2][8];
    auto ldg_feat = [&](int f, float4* buf) {
        #pragma unroll
        for (int i = 0; i < 8; ++i) {
            int linear = tid + i * NTH;       // 0..1023
            int r  = linear >> 4;             // local row
            int ch = linear & 15;             // float4 chunk
            int idx = sIdx[r * NFEAT + f];
            const float* src;
            if (f == 0)      src = user_emb + (size_t)idx * EMB;
            else if (f == 1) src = item_emb + (size_t)idx * EMB;
            else             src = sparse_tables + ((size_t)(f - 2) * SPVOC + (size_t)idx) * EMB;
            buf[i] = __ldg((const float4*)src + ch);
        }
    };
    auto sts_feat = [&](int st, const float4* buf) {
        __nv_bfloat16* A = sA + st * TILE_M * A_STR;
        #pragma unroll
        for (int i = 0; i < 8; ++i) {
            int linear = tid + i * NTH;
            int r  = linear >> 4;
            int ch = linear & 15;
            float4 v = buf[i];
            uint32_t p0 = pack_bf16x2(v.x, v.y);
            uint32_t p1 = pack_bf16x2(v.z, v.w);
            uint32_t dst = (uint32_t)__cvta_generic_to_shared(A + r * A_STR + ch * 4);
            asm volatile("st.shared.v2.b32 [%0], {%1,%2};" :: "r"(dst), "r"(p0), "r"(p1) : "memory");
        }
    };

    // ---- B cp.async into ring stage f%3 (bf16, L2-resident)
    auto cpa_b = [&](int f) {
        __nv_bfloat16* Bst = sB + (f % NBSTG) * NDIM * B_STR;
        const __nv_bfloat16* bsrc = g_W1T + f * EMB;
        #pragma unroll
        for (int i = 0; i < 8; ++i) {
            int linear = tid + i * NTH;       // 0..1023
            int n  = linear >> 3;
            int ch = linear & 7;
            cpa16(Bst + n * B_STR + ch * 8, bsrc + (size_t)n * KDIM + ch * 8);
        }
    };

    // ---- MMA over one staged feature: K=64 (4 k-steps), B frags reused for 2 m-tiles
    auto do_mma = [&](int f) {
        const __nv_bfloat16* A = sA + (f & 1) * TILE_M * A_STR;
        const __nv_bfloat16* B = sB + (f % NBSTG) * NDIM * B_STR;
        #pragma unroll
        for (int ks = 0; ks < 4; ++ks) {
            uint32_t a[2][4];
            #pragma unroll
            for (int mt = 0; mt < 2; ++mt) {
                const __nv_bfloat16* ar0 = A + (wmb + mt * 16 + g)     * A_STR + ks * 16 + 2 * tg;
                const __nv_bfloat16* ar1 = A + (wmb + mt * 16 + g + 8) * A_STR + ks * 16 + 2 * tg;
                a[mt][0] = *(const uint32_t*)ar0;
                a[mt][1] = *(const uint32_t*)ar1;
                a[mt][2] = *(const uint32_t*)(ar0 + 8);
                a[mt][3] = *(const uint32_t*)(ar1 + 8);
            }
            #pragma unroll
            for (int nt = 0; nt < 8; ++nt) {
                const __nv_bfloat16* bp = B + (nh * 64 + nt * 8 + g) * B_STR + ks * 16 + 2 * tg;
                uint32_t b0  = *(const uint32_t*)bp;
                uint32_t b1r = *(const uint32_t*)(bp + 8);
                #pragma unroll
                for (int mt = 0; mt < 2; ++mt) {
                    asm volatile(
                        "mma.sync.aligned.m16n8k16.row.col.f32.bf16.bf16.f32 "
                        "{%0,%1,%2,%3}, {%4,%5,%6,%7}, {%8,%9}, {%0,%1,%2,%3};\n"
                        : "+f"(c[mt][nt][0]), "+f"(c[mt][nt][1]),
                          "+f"(c[mt][nt][2]), "+f"(c[mt][nt][3])
                        : "r"(a[mt][0]), "r"(a[mt][1]), "r"(a[mt][2]), "r"(a[mt][3]),
                          "r"(b0), "r"(b1r));
                }
            }
        }
    };

    // ---- prologue: A regs f=0,1 ; B stages 0,1 in flight
    ldg_feat(0, abuf[0]);
    ldg_feat(1, abuf[1]);
    cpa_b(0); cpa_commit();
    cpa_b(1); cpa_commit();

    // ---- main pipeline over 28 features (one barrier per iteration)
    #pragma unroll 1
    for (int f = 0; f < NFEAT; ++f) {
        sts_feat(f & 1, abuf[f & 1]);                 // feature f -> A stage
        if (f + 2 < NFEAT) ldg_feat(f + 2, abuf[f & 1]);
        cpa_wait1();                                  // B(f) resident (B(f+1) may fly)
        __syncthreads();                              // A(f)/B(f) visible; prior reads done
        if (f + 2 < NFEAT) cpa_b(f + 2);              // refill ring stage (f+2)%3
        cpa_commit();                                 // keep group count uniform
        do_mma(f);
    }

    // ---- Epilogue: bias + ReLU + dot(W2), per n-half partials
    #pragma unroll
    for (int mt = 0; mt < 2; ++mt) {
        float acc0 = 0.f, acc1 = 0.f;                 // rows wmb+mt*16+g, +8
        #pragma unroll
        for (int nt = 0; nt < 8; ++nt) {
            int n0 = nh * 64 + nt * 8 + 2 * tg;
            float bias0 = __ldg(b1 + n0);
            float bias1 = __ldg(b1 + n0 + 1);
            float w0 = __ldg(W2 + n0);
            float w1 = __ldg(W2 + n0 + 1);
            acc0 += fmaxf(c[mt][nt][0] + bias0, 0.f) * w0;
            acc0 += fmaxf(c[mt][nt][1] + bias1, 0.f) * w1;
            acc1 += fmaxf(c[mt][nt][2] + bias0, 0.f) * w0;
            acc1 += fmaxf(c[mt][nt][3] + bias1, 0.f) * w1;
        }
        acc0 += __shfl_xor_sync(0xffffffffu, acc0, 1);
        acc0 += __shfl_xor_sync(0xffffffffu, acc0, 2);
        acc1 += __shfl_xor_sync(0xffffffffu, acc1, 1);
        acc1 += __shfl_xor_sync(0xffffffffu, acc1, 2);
        if (tg == 0) {
            sPart[(wmb + mt * 16 + g)     * 2 + nh] = acc0;
            sPart[(wmb + mt * 16 + g + 8) * 2 + nh] = acc1;
        }
    }
    __syncthreads();

    if (tid < TILE_M) {
        float x = sPart[tid * 2] + sPart[tid * 2 + 1] + __ldg(b2);
        out[row0 + tid] = 1.f / (1.f + __expf(-x));
    }
}

extern "C" void kernel_launch(void* const* d_in, const int* in_sizes, int n_in,
                              void* d_out, int out_size) {
    const int*   user_ids      = (const int*)d_in[0];
    const int*   item_ids      = (const int*)d_in[1];
    const int*   sparse        = (const int*)d_in[2];
    const float* user_emb      = (const float*)d_in[3];
    const float* item_emb      = (const float*)d_in[4];
    const float* sparse_tables = (const float*)d_in[5];
    const float* W1            = (const float*)d_in[6];
    const float* b1            = (const float*)d_in[7];
    const float* W2            = (const float*)d_in[8];
    const float* b2            = (const float*)d_in[9];
    float* out = (float*)d_out;

    cudaFuncSetAttribute(dlrm_fused_kernel,
                         cudaFuncAttributeMaxDynamicSharedMemorySize, SMEM_TOTAL);

    prep_w1_kernel<<<(NDIM * KDIM + 255) / 256, 256>>>(W1);
    dlrm_fused_kernel<<<BATCH / TILE_M, NTH, SMEM_TOTAL>>>(
        user_ids, item_ids, sparse, user_emb, item_emb, sparse_tables,
        b1, W2, b2, out);
}

// round 8
// speedup vs baseline: 1.0961x; 1.0961x over previous
#include <cuda_runtime.h>
#include <cuda_bf16.h>
#include <cstdint>
#include <cstddef>

// ---------------- Problem constants ----------------
#define BATCH    16384
#define EMB      64
#define NSP      26
#define NFEAT    28            // user + item + 26 sparse
#define KDIM     1792
#define NDIM     128
#define SPVOC    100000
#define TILE_M   64
#define NTH      256           // 8 warps: kg(2) x row-group(2) x n-half(2)
#define NBSTG    3             // B cp.async ring stages
#define A_STR    72            // bf16 row stride (64 + 8 pad) -> conflict-free
#define B_STR    72
#define X_STR    132           // fp32 exchange row stride (128 + 4)

#define SMEM_A_BYTES   (2 * TILE_M * A_STR * 2)            // 18432
#define SMEM_B_BYTES   (NBSTG * NDIM * B_STR * 2)          // 55296
#define SMEM_IDX_BYTES (TILE_M * NFEAT * 4)                // 7168
#define SMEM_PART_BYTES (TILE_M * 2 * 4)                   // 512
#define SMEM_TOTAL (SMEM_A_BYTES + SMEM_B_BYTES + SMEM_IDX_BYTES + SMEM_PART_BYTES)

// Pre-transposed bf16 copy of W1: g_W1T[n][k]  (n-major, k contiguous)
__device__ __nv_bfloat16 g_W1T[NDIM * KDIM];

__global__ void prep_w1_kernel(const float* __restrict__ W1) {
    int i = blockIdx.x * blockDim.x + threadIdx.x;
    if (i < NDIM * KDIM) {
        int n = i / KDIM;
        int k = i - n * KDIM;
        g_W1T[i] = __float2bfloat16(W1[(size_t)k * NDIM + n]);
    }
}

// ---------------- PTX helpers ----------------
__device__ __forceinline__ void cpa16(void* smem, const void* gmem) {
    uint32_t s = (uint32_t)__cvta_generic_to_shared(smem);
    asm volatile("cp.async.cg.shared.global [%0], [%1], 16;\n" :: "r"(s), "l"(gmem));
}
__device__ __forceinline__ void cpa_commit() {
    asm volatile("cp.async.commit_group;\n" ::: "memory");
}
__device__ __forceinline__ void cpa_wait1() {
    asm volatile("cp.async.wait_group 1;\n" ::: "memory");
}
__device__ __forceinline__ uint32_t pack_bf16x2(float x, float y) {
    __nv_bfloat162 h = __floats2bfloat162_rn(x, y);
    return *(uint32_t*)&h;
}

__global__ __launch_bounds__(NTH, 2) void dlrm_fused_kernel(
    const int*   __restrict__ user_ids,
    const int*   __restrict__ item_ids,
    const int*   __restrict__ sparse,
    const float* __restrict__ user_emb,
    const float* __restrict__ item_emb,
    const float* __restrict__ sparse_tables,
    const float* __restrict__ b1,
    const float* __restrict__ W2,
    const float* __restrict__ b2,
    float*       __restrict__ out)
{
    extern __shared__ char smem_raw[];
    __nv_bfloat16* sA   = (__nv_bfloat16*)smem_raw;                  // [2][64][A_STR]
    __nv_bfloat16* sB   = (__nv_bfloat16*)(smem_raw + SMEM_A_BYTES); // [3][128][B_STR]
    int*           sIdx = (int*)(smem_raw + SMEM_A_BYTES + SMEM_B_BYTES);
    float*         sPart= (float*)(smem_raw + SMEM_A_BYTES + SMEM_B_BYTES + SMEM_IDX_BYTES);
    // fp32 exchange buffer for k-group reduction: reuses the B ring space post-mainloop
    float*         sX   = (float*)(smem_raw + SMEM_A_BYTES);         // [64][X_STR]

    const int tid  = threadIdx.x;
    const int warp = tid >> 5;
    const int lane = tid & 31;
    const int row0 = blockIdx.x * TILE_M;

    const int g    = lane >> 2;            // 0..7
    const int tg   = lane & 3;             // 0..3
    const int kg   = warp >> 2;            // 0/1: k half (2 k16-steps each)
    const int wmb  = ((warp >> 1) & 1) * 32;  // row-group base (0 or 32)
    const int nh   = warp & 1;             // n half (64 cols)

    // ---- Preload all 64x28 indices into SMEM (one round trip)
    #pragma unroll
    for (int j = 0; j < 7; ++j) {
        int linear = tid + j * NTH;          // < 1792
        int r = linear / NFEAT;
        int f = linear - r * NFEAT;
        int v;
        if (f == 0)      v = __ldg(user_ids + row0 + r);
        else if (f == 1) v = __ldg(item_ids + row0 + r);
        else             v = __ldg(sparse + (size_t)(row0 + r) * NSP + (f - 2));
        sIdx[r * NFEAT + f] = v;
    }
    __syncthreads();

    // accumulators: 2 m-tiles x 8 n-tiles x 4 (this warp's K-half partials)
    float c[2][8][4];
    #pragma unroll
    for (int mt = 0; mt < 2; ++mt)
        #pragma unroll
        for (int nt = 0; nt < 8; ++nt) {
            c[mt][nt][0] = 0.f; c[mt][nt][1] = 0.f;
            c[mt][nt][2] = 0.f; c[mt][nt][3] = 0.f;
        }

    // ---- A gather: 4 float4 per thread per feature, 2-ahead reg double buffer
    float4 abuf[2][4];
    auto ldg_feat = [&](int f, float4* buf) {
        #pragma unroll
        for (int i = 0; i < 4; ++i) {
            int linear = tid + i * NTH;       // 0..1023
            int r  = linear >> 4;             // local row
            int ch = linear & 15;             // float4 chunk
            int idx = sIdx[r * NFEAT + f];
            const float* src;
            if (f == 0)      src = user_emb + (size_t)idx * EMB;
            else if (f == 1) src = item_emb + (size_t)idx * EMB;
            else             src = sparse_tables + ((size_t)(f - 2) * SPVOC + (size_t)idx) * EMB;
            buf[i] = __ldg((const float4*)src + ch);
        }
    };
    auto sts_feat = [&](int st, const float4* buf) {
        __nv_bfloat16* A = sA + st * TILE_M * A_STR;
        #pragma unroll
        for (int i = 0; i < 4; ++i) {
            int linear = tid + i * NTH;
            int r  = linear >> 4;
            int ch = linear & 15;
            float4 v = buf[i];
            uint32_t p0 = pack_bf16x2(v.x, v.y);
            uint32_t p1 = pack_bf16x2(v.z, v.w);
            uint32_t dst = (uint32_t)__cvta_generic_to_shared(A + r * A_STR + ch * 4);
            asm volatile("st.shared.v2.b32 [%0], {%1,%2};" :: "r"(dst), "r"(p0), "r"(p1) : "memory");
        }
    };

    // ---- B cp.async into ring stage f%3 (bf16, L2-resident)
    auto cpa_b = [&](int f) {
        __nv_bfloat16* Bst = sB + (f % NBSTG) * NDIM * B_STR;
        const __nv_bfloat16* bsrc = g_W1T + f * EMB;
        #pragma unroll
        for (int i = 0; i < 4; ++i) {
            int linear = tid + i * NTH;       // 0..1023
            int n  = linear >> 3;
            int ch = linear & 7;
            cpa16(Bst + n * B_STR + ch * 8, bsrc + (size_t)n * KDIM + ch * 8);
        }
    };

    // ---- MMA over one staged feature: this warp covers 2 of the 4 k16-steps
    auto do_mma = [&](int f) {
        const __nv_bfloat16* A = sA + (f & 1) * TILE_M * A_STR;
        const __nv_bfloat16* B = sB + (f % NBSTG) * NDIM * B_STR;
        #pragma unroll
        for (int kk = 0; kk < 2; ++kk) {
            const int ks = kg * 2 + kk;
            uint32_t a[2][4];
            #pragma unroll
            for (int mt = 0; mt < 2; ++mt) {
                const __nv_bfloat16* ar0 = A + (wmb + mt * 16 + g)     * A_STR + ks * 16 + 2 * tg;
                const __nv_bfloat16* ar1 = A + (wmb + mt * 16 + g + 8) * A_STR + ks * 16 + 2 * tg;
                a[mt][0] = *(const uint32_t*)ar0;
                a[mt][1] = *(const uint32_t*)ar1;
                a[mt][2] = *(const uint32_t*)(ar0 + 8);
                a[mt][3] = *(const uint32_t*)(ar1 + 8);
            }
            #pragma unroll
            for (int nt = 0; nt < 8; ++nt) {
                const __nv_bfloat16* bp = B + (nh * 64 + nt * 8 + g) * B_STR + ks * 16 + 2 * tg;
                uint32_t b0  = *(const uint32_t*)bp;
                uint32_t b1r = *(const uint32_t*)(bp + 8);
                #pragma unroll
                for (int mt = 0; mt < 2; ++mt) {
                    asm volatile(
                        "mma.sync.aligned.m16n8k16.row.col.f32.bf16.bf16.f32 "
                        "{%0,%1,%2,%3}, {%4,%5,%6,%7}, {%8,%9}, {%0,%1,%2,%3};\n"
                        : "+f"(c[mt][nt][0]), "+f"(c[mt][nt][1]),
                          "+f"(c[mt][nt][2]), "+f"(c[mt][nt][3])
                        : "r"(a[mt][0]), "r"(a[mt][1]), "r"(a[mt][2]), "r"(a[mt][3]),
                          "r"(b0), "r"(b1r));
                }
            }
        }
    };

    // ---- prologue: A regs f=0,1 ; B stages 0,1 in flight
    ldg_feat(0, abuf[0]);
    ldg_feat(1, abuf[1]);
    cpa_b(0); cpa_commit();
    cpa_b(1); cpa_commit();

    // ---- main pipeline over 28 features (one barrier per iteration)
    #pragma unroll 1
    for (int f = 0; f < NFEAT; ++f) {
        sts_feat(f & 1, abuf[f & 1]);                 // feature f -> A stage
        if (f + 2 < NFEAT) ldg_feat(f + 2, abuf[f & 1]);
        cpa_wait1();                                  // B(f) resident (B(f+1) may fly)
        __syncthreads();                              // A(f)/B(f) visible; prior reads done
        if (f + 2 < NFEAT) cpa_b(f + 2);              // refill ring stage (f+2)%3
        cpa_commit();                                 // keep group count uniform
        do_mma(f);
    }

    // ---- K-group reduction: kg1 stores partials, kg0 adds (ReLU needs full sum)
    __syncthreads();                                  // all B-ring reads done; safe to reuse as sX
    if (kg == 1) {
        #pragma unroll
        for (int mt = 0; mt < 2; ++mt)
            #pragma unroll
            for (int nt = 0; nt < 8; ++nt) {
                int r0l = wmb + mt * 16 + g;
                int col = nh * 64 + nt * 8 + 2 * tg;
                sX[r0l * X_STR + col]           = c[mt][nt][0];
                sX[r0l * X_STR + col + 1]       = c[mt][nt][1];
                sX[(r0l + 8) * X_STR + col]     = c[mt][nt][2];
                sX[(r0l + 8) * X_STR + col + 1] = c[mt][nt][3];
            }
    }
    __syncthreads();

    if (kg == 0) {
        #pragma unroll
        for (int mt = 0; mt < 2; ++mt) {
            float acc0 = 0.f, acc1 = 0.f;             // rows wmb+mt*16+g, +8
            int r0l = wmb + mt * 16 + g;
            #pragma unroll
            for (int nt = 0; nt < 8; ++nt) {
                int n0 = nh * 64 + nt * 8 + 2 * tg;
                float h0 = c[mt][nt][0] + sX[r0l * X_STR + n0];
                float h1 = c[mt][nt][1] + sX[r0l * X_STR + n0 + 1];
                float h2 = c[mt][nt][2] + sX[(r0l + 8) * X_STR + n0];
                float h3 = c[mt][nt][3] + sX[(r0l + 8) * X_STR + n0 + 1];
                float bias0 = __ldg(b1 + n0);
                float bias1 = __ldg(b1 + n0 + 1);
                float w0 = __ldg(W2 + n0);
                float w1 = __ldg(W2 + n0 + 1);
                acc0 += fmaxf(h0 + bias0, 0.f) * w0;
                acc0 += fmaxf(h1 + bias1, 0.f) * w1;
                acc1 += fmaxf(h2 + bias0, 0.f) * w0;
                acc1 += fmaxf(h3 + bias1, 0.f) * w1;
            }
            acc0 += __shfl_xor_sync(0xffffffffu, acc0, 1);
            acc0 += __shfl_xor_sync(0xffffffffu, acc0, 2);
            acc1 += __shfl_xor_sync(0xffffffffu, acc1, 1);
            acc1 += __shfl_xor_sync(0xffffffffu, acc1, 2);
            if (tg == 0) {
                sPart[r0l * 2 + nh]       = acc0;
                sPart[(r0l + 8) * 2 + nh] = acc1;
            }
        }
    }
    __syncthreads();

    if (tid < TILE_M) {
        float x = sPart[tid * 2] + sPart[tid * 2 + 1] + __ldg(b2);
        out[row0 + tid] = 1.f / (1.f + __expf(-x));
    }
}

extern "C" void kernel_launch(void* const* d_in, const int* in_sizes, int n_in,
                              void* d_out, int out_size) {
    const int*   user_ids      = (const int*)d_in[0];
    const int*   item_ids      = (const int*)d_in[1];
    const int*   sparse        = (const int*)d_in[2];
    const float* user_emb      = (const float*)d_in[3];
    const float* item_emb      = (const float*)d_in[4];
    const float* sparse_tables = (const float*)d_in[5];
    const float* W1            = (const float*)d_in[6];
    const float* b1            = (const float*)d_in[7];
    const float* W2            = (const float*)d_in[8];
    const float* b2            = (const float*)d_in[9];
    float* out = (float*)d_out;

    cudaFuncSetAttribute(dlrm_fused_kernel,
                         cudaFuncAttributeMaxDynamicSharedMemorySize, SMEM_TOTAL);

    prep_w1_kernel<<<(NDIM * KDIM + 255) / 256, 256>>>(W1);
    dlrm_fused_kernel<<<BATCH / TILE_M, NTH, SMEM_TOTAL>>>(
        user_ids, item_ids, sparse, user_emb, item_emb, sparse_tables,
        b1, W2, b2, out);
}

// round 9
// speedup vs baseline: 1.5242x; 1.3906x over previous
#include <cuda_runtime.h>
#include <cuda_bf16.h>
#include <cstdint>
#include <cstddef>

// ---------------- Problem constants ----------------
#define BATCH    16384
#define EMB      64
#define NSP      26
#define NFEAT    28            // user + item + 26 sparse
#define KDIM     1792
#define NDIM     128
#define SPVOC    100000
#define TILE_M   64
#define NTH      256           // 8 warps: kg(2) x rg(2) x nh(2)
#define NSTG     3             // ring stages (A and B)
#define A_ROW_B  144           // fp32 row: 32 floats (128B) + 16B pad, 16B-aligned
#define A_SLOT_B (32 * A_ROW_B)        // 4608 B per (kg,rg) stage
#define B_SLOT_B 4096                  // per (kg,nh) stage: [kk][nt][lane][2]u32
#define X_STR    132

#define OFF_A    0
#define SZ_A     (4 * NSTG * A_SLOT_B)           // 55296
#define OFF_B    SZ_A
#define SZ_B     (4 * NSTG * B_SLOT_B)           // 49152
#define OFF_IDX  (OFF_B + SZ_B)                  // 104448
#define SZ_IDX   (TILE_M * NFEAT * 4)            // 7168
#define OFF_PART (OFF_IDX + SZ_IDX)              // 111616
#define SMEM_TOTAL (OFF_PART + TILE_M * 2 * 4)   // 112128

// W1 pre-packed in mma B-fragment order:
// idx = ((((f*4 + kg*2+nh)*2 + kk)*8 + nt)*32 + lane)*2 + j
// val = pack_bf16(W1[k][n], W1[k+1][n]); n = nh*64+nt*8+(lane>>2);
// k = f*64 + kg*32 + kk*16 + (lane&3)*2 + j*8
__device__ uint32_t g_W1frag[NFEAT * 4 * 2 * 8 * 32 * 2];   // 448 KB

__global__ void prep_w1frag(const float* __restrict__ W1) {
    int i = blockIdx.x * blockDim.x + threadIdx.x;
    if (i >= NFEAT * 4096) return;
    int j    = i & 1;
    int lane = (i >> 1) & 31;
    int nt   = (i >> 6) & 7;
    int kk   = (i >> 9) & 1;
    int pgb  = (i >> 10) & 3;
    int f    = i >> 12;
    int kg = pgb >> 1, nh = pgb & 1;
    int n = nh * 64 + nt * 8 + (lane >> 2);
    int k = f * 64 + kg * 32 + kk * 16 + (lane & 3) * 2 + j * 8;
    __nv_bfloat162 h = __floats2bfloat162_rn(W1[(size_t)k * NDIM + n],
                                             W1[(size_t)(k + 1) * NDIM + n]);
    g_W1frag[i] = *(uint32_t*)&h;
}

// ---------------- PTX helpers ----------------
__device__ __forceinline__ void cpa16(uint32_t s, const void* g) {
    asm volatile("cp.async.cg.shared.global [%0], [%1], 16;\n" :: "r"(s), "l"(g));
}
__device__ __forceinline__ void cpa_commit() {
    asm volatile("cp.async.commit_group;\n" ::: "memory");
}
__device__ __forceinline__ void cpa_wait1() {
    asm volatile("cp.async.wait_group 1;\n" ::: "memory");
}
__device__ __forceinline__ void barx(int id) {
    asm volatile("bar.sync %0, 64;" :: "r"(id) : "memory");
}
__device__ __forceinline__ uint32_t lds_pack(uint32_t addr) {   // fp32x2 -> bf16x2
    float x, y;
    asm volatile("ld.shared.v2.f32 {%0,%1}, [%2];" : "=f"(x), "=f"(y) : "r"(addr));
    __nv_bfloat162 h = __floats2bfloat162_rn(x, y);
    return *(uint32_t*)&h;
}

__global__ __launch_bounds__(NTH, 2) void dlrm_fused_kernel(
    const int*   __restrict__ user_ids,
    const int*   __restrict__ item_ids,
    const int*   __restrict__ sparse,
    const float* __restrict__ user_emb,
    const float* __restrict__ item_emb,
    const float* __restrict__ sparse_tables,
    const float* __restrict__ b1,
    const float* __restrict__ W2,
    const float* __restrict__ b2,
    float*       __restrict__ out)
{
    extern __shared__ __align__(16) char smem_raw[];
    int*   sIdx  = (int*)(smem_raw + OFF_IDX);
    float* sPart = (float*)(smem_raw + OFF_PART);
    float* sX    = (float*)(smem_raw + OFF_A);    // reused post-mainloop

    const uint32_t sb = (uint32_t)__cvta_generic_to_shared(smem_raw);

    const int tid  = threadIdx.x;
    const int warp = tid >> 5;
    const int lane = tid & 31;
    const int row0 = blockIdx.x * TILE_M;

    const int g   = lane >> 2;          // 0..7
    const int tg  = lane & 3;           // 0..3
    const int kg  = warp >> 2;          // k half
    const int rg  = (warp >> 1) & 1;    // row group (32 rows)
    const int nh  = warp & 1;           // n half (64 cols)
    const int pga = kg * 2 + rg;        // A share group (nh siblings)
    const int pgb = kg * 2 + nh;        // B share group (rg siblings)

    const uint32_t aBase = sb + OFF_A + pga * NSTG * A_SLOT_B;
    const uint32_t bBase = sb + OFF_B + pgb * NSTG * B_SLOT_B;

    // ---- Preload all 64x28 indices into SMEM (one round trip)
    #pragma unroll
    for (int j = 0; j < 7; ++j) {
        int linear = tid + j * NTH;          // < 1792
        int r = linear / NFEAT;
        int f = linear - r * NFEAT;
        int v;
        if (f == 0)      v = __ldg(user_ids + row0 + r);
        else if (f == 1) v = __ldg(item_ids + row0 + r);
        else             v = __ldg(sparse + (size_t)(row0 + r) * NSP + (f - 2));
        sIdx[r * NFEAT + f] = v;
    }
    __syncthreads();

    // accumulators: 2 m-tiles x 8 n-tiles x 4 (K-half partials)
    float c[2][8][4];
    #pragma unroll
    for (int mt = 0; mt < 2; ++mt)
        #pragma unroll
        for (int nt = 0; nt < 8; ++nt) {
            c[mt][nt][0] = 0.f; c[mt][nt][1] = 0.f;
            c[mt][nt][2] = 0.f; c[mt][nt][3] = 0.f;
        }

    // ---- per-feature cp.async: 4x16B A (fp32 gather half-rows) + 4x16B B (frag-packed)
    auto cpa_feat = [&](int f) {
        const int st = f % NSTG;
        const uint32_t aslot = aBase + st * A_SLOT_B;
        #pragma unroll
        for (int i = 0; i < 4; ++i) {
            int linear = lane + i * 32;       // 0..127
            int r16 = linear >> 3;            // 0..15
            int ch  = linear & 7;             // 16B chunk in 128B half-row
            int lrow = nh * 16 + r16;         // 0..31 within (kg,rg) slot
            int idx  = sIdx[(rg * 32 + lrow) * NFEAT + f];
            const float* src;
            if (f == 0)      src = user_emb + (size_t)idx * EMB;
            else if (f == 1) src = item_emb + (size_t)idx * EMB;
            else             src = sparse_tables + ((size_t)(f - 2) * SPVOC + (size_t)idx) * EMB;
            cpa16(aslot + lrow * A_ROW_B + ch * 16, src + kg * 32 + ch * 4);
        }
        const uint32_t bslot = bBase + st * B_SLOT_B + rg * 2048;
        const char* bsrc = (const char*)g_W1frag + ((size_t)f * 4 + pgb) * 4096 + rg * 2048;
        #pragma unroll
        for (int i = 0; i < 4; ++i) {
            int off = (lane + i * 32) * 16;
            cpa16(bslot + off, bsrc + off);
        }
    };

    // ---- prologue: 2 features in flight
    cpa_feat(0); cpa_commit();
    cpa_feat(1); cpa_commit();

    // ---- mainloop: NO __syncthreads; pairwise named barriers only
    #pragma unroll 1
    for (int f = 0; f < NFEAT; ++f) {
        cpa_wait1();                   // my stage-f copies arrived
        barx(1 + pga);                 // nh-sibling too; its stage f-1 reads done
        barx(5 + pgb);                 // rg-sibling too
        if (f + 2 < NFEAT) cpa_feat(f + 2);
        cpa_commit();                  // uniform group cadence

        const int st = f % NSTG;
        const uint32_t aslot = aBase + st * A_SLOT_B;
        const uint32_t bslot = bBase + st * B_SLOT_B;

        #pragma unroll
        for (int kk = 0; kk < 2; ++kk) {
            uint32_t a[2][4];
            #pragma unroll
            for (int mt = 0; mt < 2; ++mt) {
                uint32_t r0a = aslot + (mt * 16 + g)     * A_ROW_B + (kk * 16 + 2 * tg) * 4;
                uint32_t r1a = aslot + (mt * 16 + g + 8) * A_ROW_B + (kk * 16 + 2 * tg) * 4;
                a[mt][0] = lds_pack(r0a);
                a[mt][1] = lds_pack(r1a);
                a[mt][2] = lds_pack(r0a + 32);
                a[mt][3] = lds_pack(r1a + 32);
            }
            #pragma unroll
            for (int nt = 0; nt < 8; ++nt) {
                uint32_t b0, b1r;
                asm volatile("ld.shared.v2.b32 {%0,%1}, [%2];"
                             : "=r"(b0), "=r"(b1r)
                             : "r"(bslot + ((kk * 8 + nt) * 32 + lane) * 8));
                #pragma unroll
                for (int mt = 0; mt < 2; ++mt) {
                    asm volatile(
                        "mma.sync.aligned.m16n8k16.row.col.f32.bf16.bf16.f32 "
                        "{%0,%1,%2,%3}, {%4,%5,%6,%7}, {%8,%9}, {%0,%1,%2,%3};\n"
                        : "+f"(c[mt][nt][0]), "+f"(c[mt][nt][1]),
                          "+f"(c[mt][nt][2]), "+f"(c[mt][nt][3])
                        : "r"(a[mt][0]), "r"(a[mt][1]), "r"(a[mt][2]), "r"(a[mt][3]),
                          "r"(b0), "r"(b1r));
                }
            }
        }
    }

    // ---- K-group reduction (ReLU needs full sum): kg1 stores, kg0 reduces
    __syncthreads();                  // all stage reads done; reuse A region as sX
    if (kg == 1) {
        #pragma unroll
        for (int mt = 0; mt < 2; ++mt)
            #pragma unroll
            for (int nt = 0; nt < 8; ++nt) {
                int r0l = rg * 32 + mt * 16 + g;
                int col = nh * 64 + nt * 8 + 2 * tg;
                sX[r0l * X_STR + col]           = c[mt][nt][0];
                sX[r0l * X_STR + col + 1]       = c[mt][nt][1];
                sX[(r0l + 8) * X_STR + col]     = c[mt][nt][2];
                sX[(r0l + 8) * X_STR + col + 1] = c[mt][nt][3];
            }
    }
    __syncthreads();

    if (kg == 0) {
        #pragma unroll
        for (int mt = 0; mt < 2; ++mt) {
            float acc0 = 0.f, acc1 = 0.f;
            int r0l = rg * 32 + mt * 16 + g;
            #pragma unroll
            for (int nt = 0; nt < 8; ++nt) {
                int n0 = nh * 64 + nt * 8 + 2 * tg;
                float h0 = c[mt][nt][0] + sX[r0l * X_STR + n0];
                float h1 = c[mt][nt][1] + sX[r0l * X_STR + n0 + 1];
                float h2 = c[mt][nt][2] + sX[(r0l + 8) * X_STR + n0];
                float h3 = c[mt][nt][3] + sX[(r0l + 8) * X_STR + n0 + 1];
                float bias0 = __ldg(b1 + n0);
                float bias1 = __ldg(b1 + n0 + 1);
                float w0 = __ldg(W2 + n0);
                float w1 = __ldg(W2 + n0 + 1);
                acc0 += fmaxf(h0 + bias0, 0.f) * w0;
                acc0 += fmaxf(h1 + bias1, 0.f) * w1;
                acc1 += fmaxf(h2 + bias0, 0.f) * w0;
                acc1 += fmaxf(h3 + bias1, 0.f) * w1;
            }
            acc0 += __shfl_xor_sync(0xffffffffu, acc0, 1);
            acc0 += __shfl_xor_sync(0xffffffffu, acc0, 2);
            acc1 += __shfl_xor_sync(0xffffffffu, acc1, 1);
            acc1 += __shfl_xor_sync(0xffffffffu, acc1, 2);
            if (tg == 0) {
                sPart[r0l * 2 + nh]       = acc0;
                sPart[(r0l + 8) * 2 + nh] = acc1;
            }
        }
    }
    __syncthreads();

    if (tid < TILE_M) {
        float x = sPart[tid * 2] + sPart[tid * 2 + 1] + __ldg(b2);
        out[row0 + tid] = 1.f / (1.f + __expf(-x));
    }
}

extern "C" void kernel_launch(void* const* d_in, const int* in_sizes, int n_in,
                              void* d_out, int out_size) {
    const int*   user_ids      = (const int*)d_in[0];
    const int*   item_ids      = (const int*)d_in[1];
    const int*   sparse        = (const int*)d_in[2];
    const float* user_emb      = (const float*)d_in[3];
    const float* item_emb      = (const float*)d_in[4];
    const float* sparse_tables = (const float*)d_in[5];
    const float* W1            = (const float*)d_in[6];
    const float* b1            = (const float*)d_in[7];
    const float* W2            = (const float*)d_in[8];
    const float* b2            = (const float*)d_in[9];
    float* out = (float*)d_out;

    cudaFuncSetAttribute(dlrm_fused_kernel,
                         cudaFuncAttributeMaxDynamicSharedMemorySize, SMEM_TOTAL);

    prep_w1frag<<<(NFEAT * 4096 + 255) / 256, 256>>>(W1);
    dlrm_fused_kernel<<<BATCH / TILE_M, NTH, SMEM_TOTAL>>>(
        user_ids, item_ids, sparse, user_emb, item_emb, sparse_tables,
        b1, W2, b2, out);
}